// round 6
// baseline (speedup 1.0000x reference)
#include <cuda_runtime.h>
#include <cstdint>

#define NN 100000
#define SUBJ_F 1000
#define DEMO_F 10
#define H1 512
#define H2 256
#define HG 128

// ---------------- scratch (static device globals; no allocation) ----------------
__device__ float g_h[(size_t)NN * H1];      // 204.8 MB
__device__ float g_xt[(size_t)NN * HG];     //  51.2 MB
__device__ float g_agg[(size_t)NN * HG];    //  51.2 MB
__device__ float g_deg[NN];
__device__ float g_dinv[NN];
__device__ float g_scratch;
// prepared weights
__device__ float g_w1hi[SUBJ_F * H1];       // 2 MB
__device__ float g_w1lo[SUBJ_F * H1];
__device__ float g_wchi[H1 * HG];           // 256 KB
__device__ float g_wclo[H1 * HG];
__device__ float g_bc[HG];

// ---------------- helpers -------------------------------------------------------
__device__ __forceinline__ uint32_t f32_to_tf32_rna(float x) {
    uint32_t o;
    asm("cvt.rna.tf32.f32 %0, %1;" : "=r"(o) : "f"(x));
    return o;
}
__device__ __forceinline__ void cp16(uint32_t daddr, const float* src, int sbytes) {
    asm volatile("cp.async.cg.shared.global [%0], [%1], 16, %2;\n"
                 :: "r"(daddr), "l"(src), "r"(sbytes));
}

// ---------------- weight prep kernels -------------------------------------------
__global__ void k_split_w(const float* __restrict__ w, float* __restrict__ hi,
                          float* __restrict__ lo, int n)
{
    int i = blockIdx.x * blockDim.x + threadIdx.x;
    if (i < n) {
        float v = w[i];
        float hf = __uint_as_float(f32_to_tf32_rna(v));
        hi[i] = hf;
        lo[i] = __uint_as_float(f32_to_tf32_rna(v - hf));
    }
}

// Wc[r][c] = sum_k W2[r][k] * Wg[k][c]; store split. grid=H1 blocks, HG threads.
__global__ void k_prep_wc(const float* __restrict__ W2, const float* __restrict__ Wg,
                          float* __restrict__ hi, float* __restrict__ lo)
{
    int r = blockIdx.x, c = threadIdx.x;
    float s = 0.f;
    for (int k = 0; k < H2; k++) s = fmaf(W2[r * H2 + k], Wg[k * HG + c], s);
    float hf = __uint_as_float(f32_to_tf32_rna(s));
    hi[r * HG + c] = hf;
    lo[r * HG + c] = __uint_as_float(f32_to_tf32_rna(s - hf));
}

__global__ void k_prep_bc(const float* __restrict__ b2, const float* __restrict__ Wg,
                          float* __restrict__ bc)
{
    int c = threadIdx.x;
    float s = 0.f;
    for (int k = 0; k < H2; k++) s = fmaf(b2[k], Wg[k * HG + c], s);
    bc[c] = s;
}

// ---------------- pipelined tf32 split-B GEMM -----------------------------------
// C[M,N] = A[M,K] @ (Bhi+Blo)[K,N] (+bias)(relu).
// CTA 128x128x32, 256 thr, warp tile 64x32, mma m16n8k8 tf32, fp32 accum.
// B double-buffered via cp.async; A register-prefetched, tf32-RNA at STS.
// Protocol: issue stage t+1 AFTER the barrier ending tile t-1's mma (no WAR race);
// wait_group 1 mid-loop (newest stage stays in flight), wait_group 0 on last tile.
#define TBM 128
#define TBN 128
#define TBK 32
#define BROW 132            // padded row length in words

#define SMEM_WORDS (5 * TBK * BROW)       // As + 2 stages x (Bhi,Blo)
#define SMEM_BYTES (SMEM_WORDS * 4)       // 84480

__global__ __launch_bounds__(256, 2)
void tgemm2_kernel(const float* __restrict__ A, int lda,
                   const float* __restrict__ Bhi, const float* __restrict__ Blo, int ldb,
                   float* __restrict__ C, int ldc,
                   int M, int K,
                   const float* __restrict__ bias, int do_relu)
{
    extern __shared__ uint32_t smem[];
    uint32_t smem_u32;
    {
        size_t p = __cvta_generic_to_shared(smem);
        smem_u32 = (uint32_t)p;
    }

    const int tid  = threadIdx.x;
    const int lane = tid & 31;
    const int wid  = tid >> 5;
    const int bm = blockIdx.y * TBM;
    const int bn = blockIdx.x * TBN;

    const int warpM = (wid >> 2) * 64;
    const int warpN = (wid & 3) * 32;
    const int grp = lane >> 2;
    const int tig = lane & 3;

    // A loader: 2 threads/row, 16 consecutive k each
    const int arow = tid >> 1;
    const int akb  = (tid & 1) * 16;
    // B loader: 8 threads per k-row, 16 cols each (4 x 16B)
    const int bkr = tid >> 3;
    const int bnb = (tid & 7) * 16;

    const int grow = bm + arow;
    const bool arow_ok = (grow < M);
    const float* Arow = A + (size_t)grow * lda;

    const int T = (K + TBK - 1) / TBK;

    // issue one B stage (hi+lo) via cp.async
    auto issueB = [&](int t, int st) {
        int gk = t * TBK + bkr;
        int sb = (gk < K) ? 16 : 0;
        int gkc = (gk < K) ? gk : (K - 1);
        const float* ph = Bhi + (size_t)gkc * ldb + bn + bnb;
        const float* pl = Blo + (size_t)gkc * ldb + bn + bnb;
        uint32_t baseB = smem_u32 + TBK * BROW * 4;  // after As
        uint32_t dh = baseB + (uint32_t)(((st * 2 + 0) * TBK + bkr) * BROW + bnb) * 4;
        uint32_t dl = baseB + (uint32_t)(((st * 2 + 1) * TBK + bkr) * BROW + bnb) * 4;
#pragma unroll
        for (int j = 0; j < 4; j++) {
            cp16(dh + 16u * j, ph + 4 * j, sb);
            cp16(dl + 16u * j, pl + 4 * j, sb);
        }
    };

    float av[16];
    auto loadA = [&](int t) {
#pragma unroll
        for (int j = 0; j < 8; j++) {
            int gk = t * TBK + akb + 2 * j;
            float2 v = make_float2(0.f, 0.f);
            if (arow_ok && gk < K) v = *reinterpret_cast<const float2*>(Arow + gk);
            av[2 * j] = v.x; av[2 * j + 1] = v.y;
        }
    };

    float acc[4][4][4];
#pragma unroll
    for (int i = 0; i < 4; i++)
#pragma unroll
        for (int j = 0; j < 4; j++)
#pragma unroll
            for (int r = 0; r < 4; r++) acc[i][j][r] = 0.f;

    // prologue: stage 0 in flight, A tile 0 in regs
    issueB(0, 0);
    asm volatile("cp.async.commit_group;\n");
    loadA(0);

    for (int t = 0; t < T; t++) {
        int st = t & 1;
        bool more = (t + 1 < T);

        __syncthreads();   // tile t-1 mma fully done: As and stage st^1 reusable

        // store A regs -> As (tf32 rounded)
#pragma unroll
        for (int i = 0; i < 16; i++)
            smem[(akb + i) * BROW + arow] = f32_to_tf32_rna(av[i]);

        if (more) {
            issueB(t + 1, st ^ 1);                  // safe: barrier above
            asm volatile("cp.async.commit_group;\n");
            loadA(t + 1);                           // overlaps with mma below
        }

        if (more) asm volatile("cp.async.wait_group 1;\n");  // stage st resident
        else      asm volatile("cp.async.wait_group 0;\n");  // last stage resident
        __syncthreads();

        const uint32_t* Bhi_s = smem + TBK * BROW + (st * 2 + 0) * TBK * BROW;
        const uint32_t* Blo_s = smem + TBK * BROW + (st * 2 + 1) * TBK * BROW;

#pragma unroll
        for (int kk = 0; kk < TBK; kk += 8) {
            uint32_t af[4][4], bh[4][2], bl[4][2];
#pragma unroll
            for (int i = 0; i < 4; i++) {
                int r0 = warpM + i * 16 + grp;
                af[i][0] = smem[(kk + tig) * BROW + r0];
                af[i][1] = smem[(kk + tig) * BROW + r0 + 8];
                af[i][2] = smem[(kk + tig + 4) * BROW + r0];
                af[i][3] = smem[(kk + tig + 4) * BROW + r0 + 8];
            }
#pragma unroll
            for (int n = 0; n < 4; n++) {
                int c0 = warpN + n * 8 + grp;
                bh[n][0] = Bhi_s[(kk + tig) * BROW + c0];
                bh[n][1] = Bhi_s[(kk + tig + 4) * BROW + c0];
                bl[n][0] = Blo_s[(kk + tig) * BROW + c0];
                bl[n][1] = Blo_s[(kk + tig + 4) * BROW + c0];
            }
#pragma unroll
            for (int i = 0; i < 4; i++)
#pragma unroll
                for (int n = 0; n < 4; n++) {
                    asm volatile(
                        "mma.sync.aligned.m16n8k8.row.col.f32.tf32.tf32.f32 "
                        "{%0,%1,%2,%3}, {%4,%5,%6,%7}, {%8,%9}, {%0,%1,%2,%3};\n"
                        : "+f"(acc[i][n][0]), "+f"(acc[i][n][1]),
                          "+f"(acc[i][n][2]), "+f"(acc[i][n][3])
                        : "r"(af[i][0]), "r"(af[i][1]), "r"(af[i][2]), "r"(af[i][3]),
                          "r"(bh[n][0]), "r"(bh[n][1]));
                    asm volatile(
                        "mma.sync.aligned.m16n8k8.row.col.f32.tf32.tf32.f32 "
                        "{%0,%1,%2,%3}, {%4,%5,%6,%7}, {%8,%9}, {%0,%1,%2,%3};\n"
                        : "+f"(acc[i][n][0]), "+f"(acc[i][n][1]),
                          "+f"(acc[i][n][2]), "+f"(acc[i][n][3])
                        : "r"(af[i][0]), "r"(af[i][1]), "r"(af[i][2]), "r"(af[i][3]),
                          "r"(bl[n][0]), "r"(bl[n][1]));
                }
        }
    }

    // epilogue
#pragma unroll
    for (int i = 0; i < 4; i++) {
#pragma unroll
        for (int n = 0; n < 4; n++) {
            int col = bn + warpN + n * 8 + tig * 2;
            float bx = 0.f, by = 0.f;
            if (bias) { bx = bias[col]; by = bias[col + 1]; }
            int row0 = bm + warpM + i * 16 + grp;
            int row1 = row0 + 8;
            if (row0 < M) {
                float vx = acc[i][n][0] + bx, vy = acc[i][n][1] + by;
                if (do_relu) { vx = fmaxf(vx, 0.f); vy = fmaxf(vy, 0.f); }
                *reinterpret_cast<float2*>(C + (size_t)row0 * ldc + col) = make_float2(vx, vy);
            }
            if (row1 < M) {
                float vx = acc[i][n][2] + bx, vy = acc[i][n][3] + by;
                if (do_relu) { vx = fmaxf(vx, 0.f); vy = fmaxf(vy, 0.f); }
                *reinterpret_cast<float2*>(C + (size_t)row1 * ldc + col) = make_float2(vx, vy);
            }
        }
    }
}

// ---------------- small FFMA GEMM (K=10 demo part, accumulates into C) ----------
#define BM 128
#define BN 128
#define BK 8

__global__ __launch_bounds__(256, 2)
void sgemm_kernel(const float* __restrict__ A, int lda,
                  const float* __restrict__ B, int ldb,
                  float* __restrict__ C, int ldc,
                  int M, int N, int K,
                  const float* __restrict__ bias,
                  int do_relu, int accum)
{
    __shared__ float As[BK][BM];
    __shared__ float Bs[BK][BN];

    const int bm = blockIdx.y * BM;
    const int bn = blockIdx.x * BN;
    const int tid = threadIdx.x;

    const int arow = tid >> 1;
    const int ak   = (tid & 1) * 4;
    const int brow = tid >> 5;
    const int bcol = (tid & 31) * 4;

    const int ty = tid >> 4;
    const int tx = tid & 15;

    float acc[8][8];
#pragma unroll
    for (int i = 0; i < 8; i++)
#pragma unroll
        for (int j = 0; j < 8; j++) acc[i][j] = 0.f;

    const int grow = bm + arow;

    for (int kt = 0; kt < K; kt += BK) {
        float av[4];
#pragma unroll
        for (int i = 0; i < 4; i++) {
            int gk = kt + ak + i;
            av[i] = (grow < M && gk < K) ? A[(size_t)grow * lda + gk] : 0.f;
        }
#pragma unroll
        for (int i = 0; i < 4; i++) As[ak + i][arow] = av[i];

        float4 bv = make_float4(0.f, 0.f, 0.f, 0.f);
        int gk = kt + brow;
        if (gk < K) bv = *reinterpret_cast<const float4*>(&B[(size_t)gk * ldb + bn + bcol]);
        *reinterpret_cast<float4*>(&Bs[brow][bcol]) = bv;

        __syncthreads();

#pragma unroll
        for (int kk = 0; kk < BK; kk++) {
            float a[8], b[8];
#pragma unroll
            for (int i = 0; i < 8; i++) a[i] = As[kk][ty * 8 + i];
#pragma unroll
            for (int j = 0; j < 8; j++) b[j] = Bs[kk][tx * 8 + j];
#pragma unroll
            for (int i = 0; i < 8; i++)
#pragma unroll
                for (int j = 0; j < 8; j++) acc[i][j] = fmaf(a[i], b[j], acc[i][j]);
        }
        __syncthreads();
    }

#pragma unroll
    for (int i = 0; i < 8; i++) {
        int row = bm + ty * 8 + i;
        if (row >= M) continue;
#pragma unroll
        for (int j = 0; j < 8; j++) {
            int col = bn + tx * 8 + j;
            float v = acc[i][j];
            if (accum) v += C[(size_t)row * ldc + col];
            if (bias)  v += bias[col];
            if (do_relu) v = fmaxf(v, 0.f);
            C[(size_t)row * ldc + col] = v;
        }
    }
}

// ---------------- graph kernels (edge_index is int32 on device) ------------------
__global__ void k_init_deg(float* __restrict__ deg, int n)
{
    int i = blockIdx.x * blockDim.x + threadIdx.x;
    if (i < n) deg[i] = 1.0f;
    if (i == 0) g_scratch = 0.f;
}

__global__ void k_deg(const int* __restrict__ ei, int E, float* __restrict__ deg)
{
    int i = blockIdx.x * blockDim.x + threadIdx.x;
    if (i < E) atomicAdd(&deg[ei[E + i]], 1.0f);
}

__global__ void k_dinv(const float* __restrict__ deg, float* __restrict__ dinv, int n)
{
    int i = blockIdx.x * blockDim.x + threadIdx.x;
    if (i < n) dinv[i] = rsqrtf(deg[i]);
}

__global__ void k_agg_init(const float* __restrict__ xt, const float* __restrict__ dinv,
                           float* __restrict__ agg, int total)
{
    int i = blockIdx.x * blockDim.x + threadIdx.x;
    if (i < total) {
        int n = i >> 7;
        float d = dinv[n];
        agg[i] = xt[i] * d * d;
    }
}

__global__ void k_edge(const int* __restrict__ ei, int E,
                       const float* __restrict__ xt, const float* __restrict__ dinv,
                       float* __restrict__ agg)
{
    int warp = (blockIdx.x * blockDim.x + threadIdx.x) >> 5;
    int lane = threadIdx.x & 31;
    if (warp >= E) return;
    int s = ei[warp];
    int d = ei[E + warp];
    float norm = dinv[s] * dinv[d];
    const float4* xs = reinterpret_cast<const float4*>(xt + (size_t)s * HG);
    float* ad = agg + (size_t)d * HG;
    float4 v = xs[lane];
    atomicAdd(&ad[lane * 4 + 0], v.x * norm);
    atomicAdd(&ad[lane * 4 + 1], v.y * norm);
    atomicAdd(&ad[lane * 4 + 2], v.z * norm);
    atomicAdd(&ad[lane * 4 + 3], v.w * norm);
}

__global__ void k_reduce(const float* __restrict__ agg, const float* __restrict__ bg,
                         const float* __restrict__ Wo, int total)
{
    float local = 0.f;
    for (int i = blockIdx.x * blockDim.x + threadIdx.x; i < total; i += gridDim.x * blockDim.x) {
        int c = i & (HG - 1);
        float v = agg[i] + bg[c];
        if (v > 0.f) local += v * Wo[c];
    }
#pragma unroll
    for (int off = 16; off > 0; off >>= 1)
        local += __shfl_down_sync(0xffffffffu, local, off);
    __shared__ float red[8];
    int lane = threadIdx.x & 31, wid = threadIdx.x >> 5;
    if (lane == 0) red[wid] = local;
    __syncthreads();
    if (wid == 0) {
        float v = (lane < (blockDim.x >> 5)) ? red[lane] : 0.f;
#pragma unroll
        for (int off = 4; off > 0; off >>= 1)
            v += __shfl_down_sync(0xffffffffu, v, off);
        if (lane == 0) atomicAdd(&g_scratch, v);
    }
}

__global__ void k_finalize(float* __restrict__ out, const float* __restrict__ bo, int n)
{
    out[0] = g_scratch / (float)n + bo[0];
}

// ---------------- launch --------------------------------------------------------
extern "C" void kernel_launch(void* const* d_in, const int* in_sizes, int n_in,
                              void* d_out, int out_size)
{
    const float* x  = (const float*)d_in[0];
    const int*   ei = (const int*)d_in[1];
    const float* W1 = (const float*)d_in[2];
    const float* b1 = (const float*)d_in[3];
    const float* W2 = (const float*)d_in[4];
    const float* b2 = (const float*)d_in[5];
    const float* Wg = (const float*)d_in[6];
    const float* bg = (const float*)d_in[7];
    const float* Wo = (const float*)d_in[8];
    const float* bo = (const float*)d_in[9];

    const int N = in_sizes[0] / (SUBJ_F + DEMO_F);
    const int E = in_sizes[1] / 2;

    float *h, *xt, *agg, *deg, *dinv;
    float *w1hi, *w1lo, *wchi, *wclo, *bc;
    cudaGetSymbolAddress((void**)&h,    g_h);
    cudaGetSymbolAddress((void**)&xt,   g_xt);
    cudaGetSymbolAddress((void**)&agg,  g_agg);
    cudaGetSymbolAddress((void**)&deg,  g_deg);
    cudaGetSymbolAddress((void**)&dinv, g_dinv);
    cudaGetSymbolAddress((void**)&w1hi, g_w1hi);
    cudaGetSymbolAddress((void**)&w1lo, g_w1lo);
    cudaGetSymbolAddress((void**)&wchi, g_wchi);
    cudaGetSymbolAddress((void**)&wclo, g_wclo);
    cudaGetSymbolAddress((void**)&bc,   g_bc);

    cudaFuncSetAttribute(tgemm2_kernel,
                         cudaFuncAttributeMaxDynamicSharedMemorySize, SMEM_BYTES);

    // degree / normalization
    k_init_deg<<<(N + 255) / 256, 256>>>(deg, N);
    k_deg<<<(E + 255) / 256, 256>>>(ei, E, deg);
    k_dinv<<<(N + 255) / 256, 256>>>(deg, dinv, N);

    // weight prep: W1 split; Wc = W2@Wg (split); bc = b2@Wg
    k_split_w<<<(SUBJ_F * H1 + 255) / 256, 256>>>(W1, w1hi, w1lo, SUBJ_F * H1);
    k_prep_wc<<<H1, HG>>>(W2, Wg, wchi, wclo);
    k_prep_bc<<<1, HG>>>(b2, Wg, bc);

    const int mgrid = (N + TBM - 1) / TBM;   // 782
    // h = relu(x[:, :1000] @ W1 + b1)
    tgemm2_kernel<<<dim3(H1 / TBN, mgrid), 256, SMEM_BYTES>>>(
        x, SUBJ_F + DEMO_F, w1hi, w1lo, H1, h, H1, N, SUBJ_F, b1, 1);
    // xt = h @ Wc + bc     (fused subj@Wg)
    tgemm2_kernel<<<dim3(HG / TBN, mgrid), 256, SMEM_BYTES>>>(
        h, H1, wchi, wclo, HG, xt, HG, N, H1, bc, 0);
    // xt += demo @ Wg[256:266]   (FFMA, exact)
    sgemm_kernel<<<dim3(HG / BN, (N + BM - 1) / BM), 256>>>(
        x + SUBJ_F, SUBJ_F + DEMO_F, Wg + (size_t)H2 * HG, HG, xt, HG,
        N, HG, DEMO_F, nullptr, 0, 1);

    // aggregation + pooled output
    k_agg_init<<<(N * HG + 255) / 256, 256>>>(xt, dinv, agg, N * HG);
    k_edge<<<((size_t)E * 32 + 255) / 256, 256>>>(ei, E, xt, dinv, agg);
    k_reduce<<<4096, 256>>>(agg, bg, Wo, N * HG);
    k_finalize<<<1, 1>>>((float*)d_out, bo, N);
}

// round 7
// speedup vs baseline: 1.1824x; 1.1824x over previous
#include <cuda_runtime.h>
#include <cstdint>

#define NN 100000
#define NE 1600000
#define SUBJ_F 1000
#define DEMO_F 10
#define H1 512
#define H2 256
#define HG 128

// ---------------- scratch (static device globals; no allocation) ----------------
__device__ float g_h[(size_t)NN * H1];      // 204.8 MB
__device__ float g_xt[(size_t)NN * HG];     //  51.2 MB
__device__ float g_dinv[NN];
__device__ int   g_cnt[NN];
__device__ int   g_cursor[NN];
__device__ int   g_rowstart[NN];
__device__ int   g_bsum[512];
__device__ int   g_csr[NE];
__device__ float g_scratch;
// prepared weights
__device__ float g_w1hi[SUBJ_F * H1];       // 2 MB
__device__ float g_w1lo[SUBJ_F * H1];
__device__ float g_wchi[H1 * HG];           // 256 KB
__device__ float g_wclo[H1 * HG];
__device__ float g_bc[HG];

// ---------------- helpers -------------------------------------------------------
__device__ __forceinline__ uint32_t f32_to_tf32_rna(float x) {
    uint32_t o;
    asm("cvt.rna.tf32.f32 %0, %1;" : "=r"(o) : "f"(x));
    return o;
}
__device__ __forceinline__ void cp16(uint32_t daddr, const float* src, int sbytes) {
    asm volatile("cp.async.cg.shared.global [%0], [%1], 16, %2;\n"
                 :: "r"(daddr), "l"(src), "r"(sbytes));
}

// ---------------- weight prep kernels -------------------------------------------
__global__ void k_split_w(const float* __restrict__ w, float* __restrict__ hi,
                          float* __restrict__ lo, int n)
{
    int i = blockIdx.x * blockDim.x + threadIdx.x;
    if (i < n) {
        float v = w[i];
        float hf = __uint_as_float(f32_to_tf32_rna(v));
        hi[i] = hf;
        lo[i] = __uint_as_float(f32_to_tf32_rna(v - hf));
    }
}

__global__ void k_prep_wc(const float* __restrict__ W2, const float* __restrict__ Wg,
                          float* __restrict__ hi, float* __restrict__ lo)
{
    int r = blockIdx.x, c = threadIdx.x;
    float s = 0.f;
    for (int k = 0; k < H2; k++) s = fmaf(W2[r * H2 + k], Wg[k * HG + c], s);
    float hf = __uint_as_float(f32_to_tf32_rna(s));
    hi[r * HG + c] = hf;
    lo[r * HG + c] = __uint_as_float(f32_to_tf32_rna(s - hf));
}

__global__ void k_prep_bc(const float* __restrict__ b2, const float* __restrict__ Wg,
                          float* __restrict__ bc)
{
    int c = threadIdx.x;
    float s = 0.f;
    for (int k = 0; k < H2; k++) s = fmaf(b2[k], Wg[k * HG + c], s);
    bc[c] = s;
}

// ---------------- pipelined tf32 split-B GEMM (validated R6) ---------------------
#define TBM 128
#define TBN 128
#define TBK 32
#define BROW 132

#define SMEM_WORDS (5 * TBK * BROW)
#define SMEM_BYTES (SMEM_WORDS * 4)

__global__ __launch_bounds__(256, 2)
void tgemm2_kernel(const float* __restrict__ A, int lda,
                   const float* __restrict__ Bhi, const float* __restrict__ Blo, int ldb,
                   float* __restrict__ C, int ldc,
                   int M, int K,
                   const float* __restrict__ bias, int do_relu)
{
    extern __shared__ uint32_t smem[];
    uint32_t smem_u32;
    {
        size_t p = __cvta_generic_to_shared(smem);
        smem_u32 = (uint32_t)p;
    }

    const int tid  = threadIdx.x;
    const int lane = tid & 31;
    const int wid  = tid >> 5;
    const int bm = blockIdx.y * TBM;
    const int bn = blockIdx.x * TBN;

    const int warpM = (wid >> 2) * 64;
    const int warpN = (wid & 3) * 32;
    const int grp = lane >> 2;
    const int tig = lane & 3;

    const int arow = tid >> 1;
    const int akb  = (tid & 1) * 16;
    const int bkr = tid >> 3;
    const int bnb = (tid & 7) * 16;

    const int grow = bm + arow;
    const bool arow_ok = (grow < M);
    const float* Arow = A + (size_t)grow * lda;

    const int T = (K + TBK - 1) / TBK;

    auto issueB = [&](int t, int st) {
        int gk = t * TBK + bkr;
        int sb = (gk < K) ? 16 : 0;
        int gkc = (gk < K) ? gk : (K - 1);
        const float* ph = Bhi + (size_t)gkc * ldb + bn + bnb;
        const float* pl = Blo + (size_t)gkc * ldb + bn + bnb;
        uint32_t baseB = smem_u32 + TBK * BROW * 4;
        uint32_t dh = baseB + (uint32_t)(((st * 2 + 0) * TBK + bkr) * BROW + bnb) * 4;
        uint32_t dl = baseB + (uint32_t)(((st * 2 + 1) * TBK + bkr) * BROW + bnb) * 4;
#pragma unroll
        for (int j = 0; j < 4; j++) {
            cp16(dh + 16u * j, ph + 4 * j, sb);
            cp16(dl + 16u * j, pl + 4 * j, sb);
        }
    };

    float av[16];
    auto loadA = [&](int t) {
#pragma unroll
        for (int j = 0; j < 8; j++) {
            int gk = t * TBK + akb + 2 * j;
            float2 v = make_float2(0.f, 0.f);
            if (arow_ok && gk < K) v = *reinterpret_cast<const float2*>(Arow + gk);
            av[2 * j] = v.x; av[2 * j + 1] = v.y;
        }
    };

    float acc[4][4][4];
#pragma unroll
    for (int i = 0; i < 4; i++)
#pragma unroll
        for (int j = 0; j < 4; j++)
#pragma unroll
            for (int r = 0; r < 4; r++) acc[i][j][r] = 0.f;

    issueB(0, 0);
    asm volatile("cp.async.commit_group;\n");
    loadA(0);

    for (int t = 0; t < T; t++) {
        int st = t & 1;
        bool more = (t + 1 < T);

        __syncthreads();

#pragma unroll
        for (int i = 0; i < 16; i++)
            smem[(akb + i) * BROW + arow] = f32_to_tf32_rna(av[i]);

        if (more) {
            issueB(t + 1, st ^ 1);
            asm volatile("cp.async.commit_group;\n");
            loadA(t + 1);
        }

        if (more) asm volatile("cp.async.wait_group 1;\n");
        else      asm volatile("cp.async.wait_group 0;\n");
        __syncthreads();

        const uint32_t* Bhi_s = smem + TBK * BROW + (st * 2 + 0) * TBK * BROW;
        const uint32_t* Blo_s = smem + TBK * BROW + (st * 2 + 1) * TBK * BROW;

#pragma unroll
        for (int kk = 0; kk < TBK; kk += 8) {
            uint32_t af[4][4], bh[4][2], bl[4][2];
#pragma unroll
            for (int i = 0; i < 4; i++) {
                int r0 = warpM + i * 16 + grp;
                af[i][0] = smem[(kk + tig) * BROW + r0];
                af[i][1] = smem[(kk + tig) * BROW + r0 + 8];
                af[i][2] = smem[(kk + tig + 4) * BROW + r0];
                af[i][3] = smem[(kk + tig + 4) * BROW + r0 + 8];
            }
#pragma unroll
            for (int n = 0; n < 4; n++) {
                int c0 = warpN + n * 8 + grp;
                bh[n][0] = Bhi_s[(kk + tig) * BROW + c0];
                bh[n][1] = Bhi_s[(kk + tig + 4) * BROW + c0];
                bl[n][0] = Blo_s[(kk + tig) * BROW + c0];
                bl[n][1] = Blo_s[(kk + tig + 4) * BROW + c0];
            }
#pragma unroll
            for (int i = 0; i < 4; i++)
#pragma unroll
                for (int n = 0; n < 4; n++) {
                    asm volatile(
                        "mma.sync.aligned.m16n8k8.row.col.f32.tf32.tf32.f32 "
                        "{%0,%1,%2,%3}, {%4,%5,%6,%7}, {%8,%9}, {%0,%1,%2,%3};\n"
                        : "+f"(acc[i][n][0]), "+f"(acc[i][n][1]),
                          "+f"(acc[i][n][2]), "+f"(acc[i][n][3])
                        : "r"(af[i][0]), "r"(af[i][1]), "r"(af[i][2]), "r"(af[i][3]),
                          "r"(bh[n][0]), "r"(bh[n][1]));
                    asm volatile(
                        "mma.sync.aligned.m16n8k8.row.col.f32.tf32.tf32.f32 "
                        "{%0,%1,%2,%3}, {%4,%5,%6,%7}, {%8,%9}, {%0,%1,%2,%3};\n"
                        : "+f"(acc[i][n][0]), "+f"(acc[i][n][1]),
                          "+f"(acc[i][n][2]), "+f"(acc[i][n][3])
                        : "r"(af[i][0]), "r"(af[i][1]), "r"(af[i][2]), "r"(af[i][3]),
                          "r"(bl[n][0]), "r"(bl[n][1]));
                }
        }
    }

#pragma unroll
    for (int i = 0; i < 4; i++) {
#pragma unroll
        for (int n = 0; n < 4; n++) {
            int col = bn + warpN + n * 8 + tig * 2;
            float bx = 0.f, by = 0.f;
            if (bias) { bx = bias[col]; by = bias[col + 1]; }
            int row0 = bm + warpM + i * 16 + grp;
            int row1 = row0 + 8;
            if (row0 < M) {
                float vx = acc[i][n][0] + bx, vy = acc[i][n][1] + by;
                if (do_relu) { vx = fmaxf(vx, 0.f); vy = fmaxf(vy, 0.f); }
                *reinterpret_cast<float2*>(C + (size_t)row0 * ldc + col) = make_float2(vx, vy);
            }
            if (row1 < M) {
                float vx = acc[i][n][2] + bx, vy = acc[i][n][3] + by;
                if (do_relu) { vx = fmaxf(vx, 0.f); vy = fmaxf(vy, 0.f); }
                *reinterpret_cast<float2*>(C + (size_t)row1 * ldc + col) = make_float2(vx, vy);
            }
        }
    }
}

// ---------------- small FFMA GEMM (K=10 demo part, accumulates into C) ----------
#define BM 128
#define BN 128
#define BK 8

__global__ __launch_bounds__(256, 2)
void sgemm_kernel(const float* __restrict__ A, int lda,
                  const float* __restrict__ B, int ldb,
                  float* __restrict__ C, int ldc,
                  int M, int N, int K,
                  const float* __restrict__ bias,
                  int do_relu, int accum)
{
    __shared__ float As[BK][BM];
    __shared__ float Bs[BK][BN];

    const int bm = blockIdx.y * BM;
    const int bn = blockIdx.x * BN;
    const int tid = threadIdx.x;

    const int arow = tid >> 1;
    const int ak   = (tid & 1) * 4;
    const int brow = tid >> 5;
    const int bcol = (tid & 31) * 4;

    const int ty = tid >> 4;
    const int tx = tid & 15;

    float acc[8][8];
#pragma unroll
    for (int i = 0; i < 8; i++)
#pragma unroll
        for (int j = 0; j < 8; j++) acc[i][j] = 0.f;

    const int grow = bm + arow;

    for (int kt = 0; kt < K; kt += BK) {
        float av[4];
#pragma unroll
        for (int i = 0; i < 4; i++) {
            int gk = kt + ak + i;
            av[i] = (grow < M && gk < K) ? A[(size_t)grow * lda + gk] : 0.f;
        }
#pragma unroll
        for (int i = 0; i < 4; i++) As[ak + i][arow] = av[i];

        float4 bv = make_float4(0.f, 0.f, 0.f, 0.f);
        int gk = kt + brow;
        if (gk < K) bv = *reinterpret_cast<const float4*>(&B[(size_t)gk * ldb + bn + bcol]);
        *reinterpret_cast<float4*>(&Bs[brow][bcol]) = bv;

        __syncthreads();

#pragma unroll
        for (int kk = 0; kk < BK; kk++) {
            float a[8], b[8];
#pragma unroll
            for (int i = 0; i < 8; i++) a[i] = As[kk][ty * 8 + i];
#pragma unroll
            for (int j = 0; j < 8; j++) b[j] = Bs[kk][tx * 8 + j];
#pragma unroll
            for (int i = 0; i < 8; i++)
#pragma unroll
                for (int j = 0; j < 8; j++) acc[i][j] = fmaf(a[i], b[j], acc[i][j]);
        }
        __syncthreads();
    }

#pragma unroll
    for (int i = 0; i < 8; i++) {
        int row = bm + ty * 8 + i;
        if (row >= M) continue;
#pragma unroll
        for (int j = 0; j < 8; j++) {
            int col = bn + tx * 8 + j;
            float v = acc[i][j];
            if (accum) v += C[(size_t)row * ldc + col];
            if (bias)  v += bias[col];
            if (do_relu) v = fmaxf(v, 0.f);
            C[(size_t)row * ldc + col] = v;
        }
    }
}

// ---------------- CSR build (edge_index is int32 on device) ----------------------
__global__ void k_zero(int* __restrict__ cnt, int* __restrict__ cur, int n)
{
    int i = blockIdx.x * blockDim.x + threadIdx.x;
    if (i < n) { cnt[i] = 0; cur[i] = 0; }
    if (i == 0) g_scratch = 0.f;
}

__global__ void k_count(const int* __restrict__ ei, int E, int* __restrict__ cnt)
{
    int i = blockIdx.x * blockDim.x + threadIdx.x;
    if (i < E) atomicAdd(&cnt[ei[E + i]], 1);
}

__global__ void k_dinv(const int* __restrict__ cnt, float* __restrict__ dinv, int n)
{
    int i = blockIdx.x * blockDim.x + threadIdx.x;
    if (i < n) dinv[i] = rsqrtf((float)cnt[i] + 1.0f);   // +1 self loop
}

// exclusive scan, 3 phases
__global__ void k_scan_block(const int* __restrict__ cnt, int* __restrict__ rs,
                             int* __restrict__ bsum, int n)
{
    __shared__ int sh[256];
    int i = blockIdx.x * 256 + threadIdx.x;
    int v = (i < n) ? cnt[i] : 0;
    sh[threadIdx.x] = v;
    __syncthreads();
#pragma unroll
    for (int off = 1; off < 256; off <<= 1) {
        int t = (threadIdx.x >= off) ? sh[threadIdx.x - off] : 0;
        __syncthreads();
        sh[threadIdx.x] += t;
        __syncthreads();
    }
    if (i < n) rs[i] = sh[threadIdx.x] - v;
    if (threadIdx.x == 255) bsum[blockIdx.x] = sh[255];
}

__global__ void k_scan_bsums(int* __restrict__ bsum, int nb)
{
    __shared__ int sh[512];
    int i = threadIdx.x;
    int v = (i < nb) ? bsum[i] : 0;
    sh[i] = v;
    __syncthreads();
#pragma unroll
    for (int off = 1; off < 512; off <<= 1) {
        int t = (i >= off) ? sh[i - off] : 0;
        __syncthreads();
        sh[i] += t;
        __syncthreads();
    }
    if (i < nb) bsum[i] = sh[i] - v;
}

__global__ void k_scan_add(int* __restrict__ rs, const int* __restrict__ bsum, int n)
{
    int i = blockIdx.x * 256 + threadIdx.x;
    if (i < n) rs[i] += bsum[blockIdx.x];
}

__global__ void k_fill(const int* __restrict__ ei, int E,
                       const int* __restrict__ rs, int* __restrict__ cur,
                       int* __restrict__ csr)
{
    int i = blockIdx.x * blockDim.x + threadIdx.x;
    if (i < E) {
        int s = ei[i];
        int d = ei[E + i];
        int pos = atomicAdd(&cur[d], 1);
        csr[rs[d] + pos] = s;
    }
}

// ---------------- fused aggregation + pooled output ------------------------------
// one warp per node d:
//   agg[d,:] = (sum_e xt[src_e,:]*dinv[src_e] + xt[d,:]*dinv[d]) * dinv[d]
//   partial  = sum_c relu(agg[d,c] + bg[c]) * Wo[c];  block-reduce -> g_scratch
__global__ __launch_bounds__(256)
void k_nodeagg(const float* __restrict__ xt,
               const float* __restrict__ dinv,
               const int* __restrict__ rs, const int* __restrict__ cnt,
               const int* __restrict__ csr,
               const float* __restrict__ bg, const float* __restrict__ Wo,
               int n)
{
    __shared__ float blk;
    if (threadIdx.x == 0) blk = 0.f;
    __syncthreads();

    int warp = (blockIdx.x * blockDim.x + threadIdx.x) >> 5;
    int lane = threadIdx.x & 31;

    float part = 0.f;
    if (warp < n) {
        int d = warp;
        float dd = dinv[d];
        const float4* xtv = reinterpret_cast<const float4*>(xt);

        // self term (pre-factored): xt[d]*dinv[d]
        float4 sv = xtv[(size_t)d * 32 + lane];
        float4 acc = make_float4(sv.x * dd, sv.y * dd, sv.z * dd, sv.w * dd);

        int e0 = rs[d];
        int e1 = e0 + cnt[d];
        // 1-deep software pipeline on the index/coef chain
        int s_cur = 0; float w_cur = 0.f;
        if (e0 < e1) { s_cur = csr[e0]; w_cur = dinv[s_cur]; }
        for (int e = e0; e < e1; e++) {
            int s = s_cur; float w = w_cur;
            if (e + 1 < e1) { s_cur = csr[e + 1]; w_cur = dinv[s_cur]; }
            float4 v = xtv[(size_t)s * 32 + lane];
            acc.x = fmaf(v.x, w, acc.x);
            acc.y = fmaf(v.y, w, acc.y);
            acc.z = fmaf(v.z, w, acc.z);
            acc.w = fmaf(v.w, w, acc.w);
        }

        int c = lane * 4;
        float4 bgv = *reinterpret_cast<const float4*>(bg + c);
        float4 wov = *reinterpret_cast<const float4*>(Wo + c);
        float vx = fmaf(acc.x, dd, bgv.x);
        float vy = fmaf(acc.y, dd, bgv.y);
        float vz = fmaf(acc.z, dd, bgv.z);
        float vw = fmaf(acc.w, dd, bgv.w);
        if (vx > 0.f) part = fmaf(vx, wov.x, part);
        if (vy > 0.f) part = fmaf(vy, wov.y, part);
        if (vz > 0.f) part = fmaf(vz, wov.z, part);
        if (vw > 0.f) part = fmaf(vw, wov.w, part);
    }

#pragma unroll
    for (int off = 16; off > 0; off >>= 1)
        part += __shfl_down_sync(0xffffffffu, part, off);
    if (lane == 0) atomicAdd(&blk, part);
    __syncthreads();
    if (threadIdx.x == 0) atomicAdd(&g_scratch, blk);
}

__global__ void k_finalize(float* __restrict__ out, const float* __restrict__ bo, int n)
{
    out[0] = g_scratch / (float)n + bo[0];
}

// ---------------- launch --------------------------------------------------------
extern "C" void kernel_launch(void* const* d_in, const int* in_sizes, int n_in,
                              void* d_out, int out_size)
{
    const float* x  = (const float*)d_in[0];
    const int*   ei = (const int*)d_in[1];
    const float* W1 = (const float*)d_in[2];
    const float* b1 = (const float*)d_in[3];
    const float* W2 = (const float*)d_in[4];
    const float* b2 = (const float*)d_in[5];
    const float* Wg = (const float*)d_in[6];
    const float* bg = (const float*)d_in[7];
    const float* Wo = (const float*)d_in[8];
    const float* bo = (const float*)d_in[9];

    const int N = in_sizes[0] / (SUBJ_F + DEMO_F);
    const int E = in_sizes[1] / 2;

    float *h, *xt, *dinv, *scratchf;
    int *cnt, *cur, *rs, *bsum, *csr;
    float *w1hi, *w1lo, *wchi, *wclo, *bc;
    cudaGetSymbolAddress((void**)&h,    g_h);
    cudaGetSymbolAddress((void**)&xt,   g_xt);
    cudaGetSymbolAddress((void**)&dinv, g_dinv);
    cudaGetSymbolAddress((void**)&cnt,  g_cnt);
    cudaGetSymbolAddress((void**)&cur,  g_cursor);
    cudaGetSymbolAddress((void**)&rs,   g_rowstart);
    cudaGetSymbolAddress((void**)&bsum, g_bsum);
    cudaGetSymbolAddress((void**)&csr,  g_csr);
    cudaGetSymbolAddress((void**)&w1hi, g_w1hi);
    cudaGetSymbolAddress((void**)&w1lo, g_w1lo);
    cudaGetSymbolAddress((void**)&wchi, g_wchi);
    cudaGetSymbolAddress((void**)&wclo, g_wclo);
    cudaGetSymbolAddress((void**)&bc,   g_bc);
    (void)scratchf;

    cudaFuncSetAttribute(tgemm2_kernel,
                         cudaFuncAttributeMaxDynamicSharedMemorySize, SMEM_BYTES);

    const int nblk = (N + 255) / 256;       // 391 (<=512 for bsum scan)

    // ---- CSR build + normalization ----
    k_zero<<<nblk, 256>>>(cnt, cur, N);
    k_count<<<(E + 255) / 256, 256>>>(ei, E, cnt);
    k_dinv<<<nblk, 256>>>(cnt, dinv, N);
    k_scan_block<<<nblk, 256>>>(cnt, rs, bsum, N);
    k_scan_bsums<<<1, 512>>>(bsum, nblk);
    k_scan_add<<<nblk, 256>>>(rs, bsum, N);
    k_fill<<<(E + 255) / 256, 256>>>(ei, E, rs, cur, csr);

    // ---- weight prep ----
    k_split_w<<<(SUBJ_F * H1 + 255) / 256, 256>>>(W1, w1hi, w1lo, SUBJ_F * H1);
    k_prep_wc<<<H1, HG>>>(W2, Wg, wchi, wclo);
    k_prep_bc<<<1, HG>>>(b2, Wg, bc);

    const int mgrid = (N + TBM - 1) / TBM;   // 782
    // h = relu(x[:, :1000] @ W1 + b1)
    tgemm2_kernel<<<dim3(H1 / TBN, mgrid), 256, SMEM_BYTES>>>(
        x, SUBJ_F + DEMO_F, w1hi, w1lo, H1, h, H1, N, SUBJ_F, b1, 1);
    // xt = h @ Wc + bc     (fused subj@Wg)
    tgemm2_kernel<<<dim3(HG / TBN, mgrid), 256, SMEM_BYTES>>>(
        h, H1, wchi, wclo, HG, xt, HG, N, H1, bc, 0);
    // xt += demo @ Wg[256:266]   (FFMA, exact)
    sgemm_kernel<<<dim3(HG / BN, (N + BM - 1) / BM), 256>>>(
        x + SUBJ_F, SUBJ_F + DEMO_F, Wg + (size_t)H2 * HG, HG, xt, HG,
        N, HG, DEMO_F, nullptr, 0, 1);

    // ---- fused aggregation + pooled output ----
    k_nodeagg<<<(N * 32 + 255) / 256, 256>>>(xt, dinv, rs, cnt, csr, bg, Wo, N);
    k_finalize<<<1, 1>>>((float*)d_out, bo, N);
}